// round 15
// baseline (speedup 1.0000x reference)
#include <cuda_runtime.h>
#include <cuda_bf16.h>
#include <cstdint>

#define BDIM 2
#define C 256
#define H 96
#define W 96
#define HW (H*W)          // 9216
#define MPIX (BDIM*HW)    // 18432
#define OC 256
#define NTAP 9
#define KQ (NTAP*C)       // 2304 logical K
#define KD2 (2*KQ)        // 4608 (hi | lo)
#define HP 98

// -------- scratch (static device globals; no allocations) --------
__device__ __align__(128) __nv_bfloat16 g_Wb2[(size_t)OC * KD2]; // [o][hi|lo] 2.4MB
__device__ __align__(128) float g_xT[(size_t)MPIX * C];          // NHWC x (19MB, L2-resident)
__device__ unsigned int g_qpack[NTAP * MPIX];
__device__ float4       g_w4[NTAP * MPIX];

// ---------------- PTX helpers (base ISA only) ----------------
__device__ __forceinline__ uint32_t smem_u32(const void* p) {
    uint32_t a;
    asm("{ .reg .u64 t; cvta.to.shared.u64 t, %1; cvt.u32.u64 %0, t; }" : "=r"(a) : "l"(p));
    return a;
}
__device__ __forceinline__ void cp16(uint32_t s, const void* g) {
    asm volatile("cp.async.cg.shared.global [%0], [%1], 16;" :: "r"(s), "l"(g));
}
__device__ __forceinline__ void cp_commit() {
    asm volatile("cp.async.commit_group;" ::: "memory");
}
template <int N> __device__ __forceinline__ void cp_wait() {
    asm volatile("cp.async.wait_group %0;" :: "n"(N) : "memory");
}
__device__ __forceinline__ void sts32(uint32_t a, uint32_t v) {
    asm volatile("st.shared.b32 [%0], %1;" :: "r"(a), "r"(v) : "memory");
}
__device__ __forceinline__ void ldsm_x4(uint32_t* r, uint32_t addr) {
    asm volatile("ldmatrix.sync.aligned.m8n8.x4.shared.b16 {%0,%1,%2,%3}, [%4];"
        : "=r"(r[0]), "=r"(r[1]), "=r"(r[2]), "=r"(r[3]) : "r"(addr));
}
__device__ __forceinline__ void mma16816(float* d, const uint32_t* a, const uint32_t* b) {
    asm volatile("mma.sync.aligned.m16n8k16.row.col.f32.bf16.bf16.f32 "
        "{%0,%1,%2,%3}, {%4,%5,%6,%7}, {%8,%9}, {%0,%1,%2,%3};"
        : "+f"(d[0]), "+f"(d[1]), "+f"(d[2]), "+f"(d[3])
        : "r"(a[0]), "r"(a[1]), "r"(a[2]), "r"(a[3]), "r"(b[0]), "r"(b[1]));
}
__device__ __forceinline__ unsigned long long fma2(
    unsigned long long a, unsigned long long b, unsigned long long c)
{
    unsigned long long d;
    asm("fma.rn.f32x2 %0, %1, %2, %3;" : "=l"(d) : "l"(a), "l"(b), "l"(c));
    return d;
}
__device__ __forceinline__ unsigned long long mul2(
    unsigned long long a, unsigned long long b)
{
    unsigned long long d;
    asm("mul.rn.f32x2 %0, %1, %2;" : "=l"(d) : "l"(a), "l"(b));
    return d;
}
__device__ __forceinline__ unsigned long long pack2(float v) {
    unsigned long long d;
    asm("mov.b64 %0, {%1, %1};" : "=l"(d) : "f"(v));
    return d;
}
__device__ __forceinline__ uint32_t cvt_bf16x2(float hi, float lo) {
    uint32_t r;
    asm("cvt.rn.bf16x2.f32 %0, %1, %2;" : "=r"(r) : "f"(hi), "f"(lo));
    return r;
}
__device__ __forceinline__ uint32_t swz(uint32_t off) { return off ^ ((off >> 3) & 0x70); }

// ================= Kernel 0: weight bf16 hi/lo split =================
__global__ void __launch_bounds__(256) wq_kernel(const float* __restrict__ wc)
{
    int o = blockIdx.x;
    int c = threadIdx.x;
#pragma unroll
    for (int k = 0; k < 9; k++) {
        float w = __ldg(&wc[((size_t)o*C + c)*9 + k]);
        __nv_bfloat16 hi = __float2bfloat16(w);
        __nv_bfloat16 lo = __float2bfloat16(w - __bfloat162float(hi));
        g_Wb2[(size_t)o * KD2 + k*C + c]      = hi;
        g_Wb2[(size_t)o * KD2 + KQ + k*C + c] = lo;
    }
}

// ================= Kernel 0b: NCHW -> NHWC transpose =================
__global__ void __launch_bounds__(256) tr_kernel(const float* __restrict__ x)
{
    __shared__ float tile[32][33];
    const int b   = blockIdx.z;
    const int c0  = blockIdx.y * 32;
    const int hw0 = blockIdx.x * 32;
    const int tx = threadIdx.x & 31;
    const int ty = threadIdx.x >> 5;
#pragma unroll
    for (int r = 0; r < 4; r++) {
        int c = c0 + ty + r * 8;
        tile[ty + r * 8][tx] = x[(size_t)(b * C + c) * HW + hw0 + tx];
    }
    __syncthreads();
#pragma unroll
    for (int r = 0; r < 4; r++) {
        int hw = hw0 + ty + r * 8;
        g_xT[(size_t)(b * HW + hw) * C + c0 + tx] = tile[tx][ty + r * 8];
    }
}

// ================= Kernel 1: offset conv — 1 px/lane, 2 blocks/SM =================
__global__ void __launch_bounds__(256) offset_kernel(
    const float* __restrict__ x,  const float* __restrict__ w_p,
    const float* __restrict__ b_p, const float* __restrict__ w_ad,
    const float* __restrict__ b_ad)
{
    const int tid = threadIdx.x;
    const int tx  = tid & 63;
    const int ty  = tid >> 6;
    const int m   = blockIdx.x * 64 + tx;

    __shared__ float wbuf[32][200];   // [s*8+cc][t*22 + oc], oc padded to 22
    __shared__ float red[4][21][64];

    const int b = m / HW, hw = m % HW, h = hw / W, w = hw % W;

    unsigned long long acc[11];
#pragma unroll
    for (int i = 0; i < 11; i++) acc[i] = 0ull;

    if (tid < 32) {
#pragma unroll
        for (int t = 0; t < 9; t++) wbuf[tid][t*22 + 21] = 0.f;
    }

    const float* xb = x + (size_t)b * C * HW;

#pragma unroll 1
    for (int ch = 0; ch < 8; ch++) {
        __syncthreads();
        for (int idx = tid; idx < 32 * 189; idx += 256) {
            int row = idx / 189, e = idx % 189;
            int oc = e / 9, t = e % 9;
            int c = (row >> 3) * 64 + ch * 8 + (row & 7);
            float wv = (oc < 18) ? __ldg(&w_p[((size_t)oc*C + c)*9 + t])
                                 : __ldg(&w_ad[((size_t)(oc-18)*C + c)*9 + t]);
            wbuf[row][t*22 + oc] = wv;
        }
        __syncthreads();
#pragma unroll 1
        for (int cc = 0; cc < 8; cc++) {
            const int c = ty * 64 + ch * 8 + cc;
            const float* pl = xb + (size_t)c * HW;
            float v[9];
#pragma unroll
            for (int t = 0; t < 9; t++) {
                int dh = t / 3 - 1, dw = t % 3 - 1;
                int h1 = h + dh, w1 = w + dw;
                v[t] = (h1 >= 0 && h1 < H && w1 >= 0 && w1 < W) ? __ldg(&pl[h1*W + w1]) : 0.f;
            }
            const float* wr = &wbuf[ty * 8 + cc][0];
#pragma unroll
            for (int t = 0; t < 9; t++) {
                unsigned long long a2 = pack2(v[t]);
#pragma unroll
                for (int o2 = 0; o2 < 11; o2++) {
                    unsigned long long wpair =
                        *(const unsigned long long*)&wr[t*22 + o2*2];
                    acc[o2] = fma2(wpair, a2, acc[o2]);
                }
            }
        }
    }

    __syncthreads();
#pragma unroll
    for (int o2 = 0; o2 < 11; o2++) {
        unsigned long long vv = acc[o2];
        float lo = __uint_as_float((unsigned)(vv & 0xffffffffull));
        float hi = __uint_as_float((unsigned)(vv >> 32));
        red[ty][o2*2][tx] = lo;
        if (o2 < 10) red[ty][o2*2+1][tx] = hi;
    }
    __syncthreads();
    if (ty == 0) {
        float a[21];
#pragma unroll
        for (int oc = 0; oc < 21; oc++)
            a[oc] = red[0][oc][tx] + red[1][oc][tx] + red[2][oc][tx] + red[3][oc][tx];
#pragma unroll
        for (int k = 0; k < 9; k++) {
            float pnx = (float)(k / 3) - 1.f;
            float pny = (float)(k % 3) - 1.f;
            float z   = a[18 + (k % 3)] + __ldg(&b_ad[k % 3]);
            float sig = 1.f / (1.f + expf(-z));
            float ad  = 2.f * (1.f - sig);
            float px = (float)(h + 1) + pnx + a[k]     + __ldg(&b_p[k])     + ad * pnx;
            float py = (float)(w + 1) + pny + a[9 + k] + __ldg(&b_p[9 + k]) + ad * pny;
            float fx = floorf(px), fy = floorf(py);
            int iltx = (int)fx, ilty = (int)fy;
            int ltx = min(max(iltx,     0), HP - 1), lty = min(max(ilty,     0), HP - 1);
            int rbx = min(max(iltx + 1, 0), HP - 1), rby = min(max(ilty + 1, 0), HP - 1);
            bool mx = (px < 1.f) || (px > (float)(HP - 2));
            bool my = (py < 1.f) || (py > (float)(HP - 2));
            if (mx) px = fx;
            if (my) py = fy;
            px = fminf(fmaxf(px, 0.f), (float)(HP - 1));
            py = fminf(fmaxf(py, 0.f), (float)(HP - 1));
            float dxl = 1.f + ((float)ltx - px);
            float dyl = 1.f + ((float)lty - py);
            float dxr = 1.f - ((float)rbx - px);
            float dyr = 1.f - ((float)rby - py);
            g_qpack[k*MPIX + m] = (unsigned)ltx | ((unsigned)lty << 8)
                                | ((unsigned)rbx << 16) | ((unsigned)rby << 24);
            g_w4[k*MPIX + m] = make_float4(dxl*dyl, dxr*dyr, dxl*dyr, dxr*dyl);
        }
    }
}

// ================= Kernel 2: fused sample + HMMA GEMM, prefetch-pipelined =================
// CTA: 128 m x 256 o, 512 threads (16 warps, warp tile 32m x 64o), grid 144.
// chunk = 32 channels of one tap -> 72 chunks. Tile rows are 64B wide (SW swizzled).
#define NCH 72
#define ST_AH 0
#define ST_AL 8192
#define ST_BH 16384
#define ST_BL 32768
#define STAGE 49152
#define FUSE_SMEM (2 * STAGE)    // 96KB

// register-resident A prefetch for 2 rows (one half of this thread's 4 rows)
struct APre {
    unsigned long long v[2][4];   // packed float2 corner pairs
    float w[2][4];
};

__device__ __forceinline__ void a_issue(APre& P, int tap, int c0, int m0,
                                        int rg, int cl, int h)
{
#pragma unroll
    for (int j = 0; j < 2; j++) {
        const int m_l = rg * 4 + h * 2 + j;
        const int m = m0 + m_l;
        const unsigned qp = g_qpack[tap*MPIX + m];
        const float4 g = g_w4[tap*MPIX + m];
        const int ltx = qp & 255, lty = (qp >> 8) & 255;
        const int rbx = (qp >> 16) & 255, rby = (qp >> 24) & 255;
        const bool ax  = (ltx >= 1) && (ltx <= 96);
        const bool axr = (rbx >= 1) && (rbx <= 96);
        const bool ay  = (lty >= 1) && (lty <= 96);
        const bool ayr = (rby >= 1) && (rby <= 96);
        P.w[j][0] = (ax  && ay ) ? g.x : 0.f;
        P.w[j][1] = (axr && ayr) ? g.y : 0.f;
        P.w[j][2] = (ax  && ayr) ? g.z : 0.f;
        P.w[j][3] = (axr && ay ) ? g.w : 0.f;
        const unsigned base = (unsigned)(m / HW) * (HW * C);
        const unsigned oLT = (ax  && ay ) ? base + (unsigned)((ltx-1)*W + (lty-1)) * C : base;
        const unsigned oRB = (axr && ayr) ? base + (unsigned)((rbx-1)*W + (rby-1)) * C : base;
        const unsigned oLB = (ax  && ayr) ? base + (unsigned)((ltx-1)*W + (rby-1)) * C : base;
        const unsigned oRT = (axr && ay ) ? base + (unsigned)((rbx-1)*W + (lty-1)) * C : base;
        const int cix = c0 + cl * 2;
        P.v[j][0] = *(const unsigned long long*)&g_xT[oLT + cix];
        P.v[j][1] = *(const unsigned long long*)&g_xT[oRB + cix];
        P.v[j][2] = *(const unsigned long long*)&g_xT[oLB + cix];
        P.v[j][3] = *(const unsigned long long*)&g_xT[oRT + cix];
    }
}

__device__ __forceinline__ void a_store(APre& P, uint32_t stgN, int rg, int cl, int h)
{
#pragma unroll
    for (int j = 0; j < 2; j++) {
        const int m_l = rg * 4 + h * 2 + j;
        // packed bilinear: v01 = w0*LT + w1*RB + w2*LB + w3*RT (f32x2)
        unsigned long long v01 = mul2(pack2(P.w[j][0]), P.v[j][0]);
        v01 = fma2(pack2(P.w[j][1]), P.v[j][1], v01);
        v01 = fma2(pack2(P.w[j][2]), P.v[j][2], v01);
        v01 = fma2(pack2(P.w[j][3]), P.v[j][3], v01);
        float v0 = __uint_as_float((unsigned)(v01 & 0xffffffffull));
        float v1 = __uint_as_float((unsigned)(v01 >> 32));
        uint32_t hw_ = cvt_bf16x2(v1, v0);
        __nv_bfloat162 hh = *reinterpret_cast<__nv_bfloat162*>(&hw_);
        float l0 = v0 - __bfloat162float(hh.x);
        float l1 = v1 - __bfloat162float(hh.y);
        uint32_t lw_ = cvt_bf16x2(l1, l0);
        uint32_t off = swz((uint32_t)(m_l * 64 + cl * 4));
        sts32(stgN + ST_AH + off, hw_);
        sts32(stgN + ST_AL + off, lw_);
    }
}

// B producer: hi+lo 256x32ch -> 2x16KB, 4 cp16 per thread
__device__ __forceinline__ void produce_B(uint32_t stg, int t, int tid)
{
    const char* Wb = (const char*)g_Wb2;
    const int colb = (t >> 3) * 512 + (t & 7) * 64;
#pragma unroll
    for (int j = 0; j < 4; j++) {
        int idx = tid + j * 512;            // 0..2047
        int part = idx >> 10;               // 0: hi, 1: lo
        int within = idx & 1023;
        int o = within >> 2, cc = within & 3;
        uint32_t dst = stg + ST_BH + part * 16384 + swz((uint32_t)(o * 64 + cc * 16));
        cp16(dst, Wb + (size_t)o * (KD2 * 2) + part * (KQ * 2) + colb + cc * 16);
    }
}

__global__ void __launch_bounds__(512, 1) mma_kernel(float* __restrict__ out)
{
    extern __shared__ char smem[];
    const uint32_t sb = smem_u32(smem);
    const int tid = threadIdx.x;
    const int wid = tid >> 5, lane = tid & 31;
    const int m0 = blockIdx.x * 128;

    const int wm = (wid >> 2) * 32;   // 4 m-groups of 32
    const int wn = (wid & 3) * 64;    // 4 n-groups of 64
    const int rg = tid >> 4;          // producer row group 0..31
    const int cl = tid & 15;          // producer channel pair 0..15

    float acc[2][8][4];
#pragma unroll
    for (int mi = 0; mi < 2; mi++)
#pragma unroll
        for (int ni = 0; ni < 8; ni++)
#pragma unroll
            for (int r = 0; r < 4; r++) acc[mi][ni][r] = 0.f;

    const int a_row = wm + (lane & 15);
    const int a_cb  = (lane >> 4) * 16;
    const int b_row = wn + (lane & 7) + ((lane >> 4) << 3);
    const int b_cb  = ((lane >> 3) & 1) * 16;

    // ---- prologue: chunk 0 ----
    produce_B(sb, 0, tid);
    cp_commit();
    {
        APre P;
        a_issue(P, 0, 0, m0, rg, cl, 0);
        a_store(P, sb, rg, cl, 0);
        a_issue(P, 0, 0, m0, rg, cl, 1);
        a_store(P, sb, rg, cl, 1);
    }

#pragma unroll 1
    for (int t = 0; t < NCH; t++) {
        const uint32_t stg  = sb + (t & 1) * STAGE;
        const uint32_t stgN = sb + ((t + 1) & 1) * STAGE;
        __syncthreads();                       // consume(t-1) + A(t) stores done everywhere
        if (t + 1 < NCH) produce_B(stgN, t + 1, tid);
        cp_commit();
        cp_wait<1>();                          // B(t) landed
        __syncthreads();                       // B(t) + A(t) visible

        const int tapN = (t + 1) >> 3;
        const int c0N  = ((t + 1) & 7) * 32;
        const bool more = (t + 1 < NCH);

        APre P;
        if (more) a_issue(P, tapN, c0N, m0, rg, cl, 0);   // LDGs in flight over kk=0

        const uint32_t Ah = stg + ST_AH;
        const uint32_t Al = stg + ST_AL;
        const uint32_t Bh = stg + ST_BH;
        const uint32_t Bl = stg + ST_BL;

#pragma unroll 1
        for (int kk = 0; kk < 2; kk++) {
            const int kb = kk * 32;
            uint32_t ah[2][4], al[2][4], bf[4][4];
#pragma unroll
            for (int mi = 0; mi < 2; mi++)
                ldsm_x4(ah[mi], Ah + swz((uint32_t)((a_row + mi * 16) * 64 + kb + a_cb)));
#pragma unroll
            for (int nb = 0; nb < 4; nb++)
                ldsm_x4(bf[nb], Bh + swz((uint32_t)((b_row + nb * 16) * 64 + kb + b_cb)));
#pragma unroll
            for (int mi = 0; mi < 2; mi++)
#pragma unroll
                for (int ni = 0; ni < 8; ni++)
                    mma16816(acc[mi][ni], ah[mi], &bf[ni >> 1][(ni & 1) * 2]);
#pragma unroll
            for (int mi = 0; mi < 2; mi++)
                ldsm_x4(al[mi], Al + swz((uint32_t)((a_row + mi * 16) * 64 + kb + a_cb)));
#pragma unroll
            for (int mi = 0; mi < 2; mi++)
#pragma unroll
                for (int ni = 0; ni < 8; ni++)
                    mma16816(acc[mi][ni], al[mi], &bf[ni >> 1][(ni & 1) * 2]);
#pragma unroll
            for (int nb = 0; nb < 4; nb++)
                ldsm_x4(bf[nb], Bl + swz((uint32_t)((b_row + nb * 16) * 64 + kb + b_cb)));
#pragma unroll
            for (int mi = 0; mi < 2; mi++)
#pragma unroll
                for (int ni = 0; ni < 8; ni++)
                    mma16816(acc[mi][ni], ah[mi], &bf[ni >> 1][(ni & 1) * 2]);

            // between k-steps: retire prefetched half, issue next half
            if (more) {
                a_store(P, stgN, rg, cl, kk);
                if (kk == 0) a_issue(P, tapN, c0N, m0, rg, cl, 1);
            }
        }
    }

    // ---- epilogue: two o-halves via smem transpose, coalesced stores ----
    const int b   = m0 / HW;
    const int hw0 = m0 % HW;
    float* eb = (float*)smem;                 // 128 x 132 floats = 67.6KB (fits 96KB)
    const int er = lane >> 2;
    const int ec = (lane & 3) * 2;
#pragma unroll 1
    for (int h = 0; h < 2; h++) {
        __syncthreads();
        if (((wid & 3) >> 1) == h) {
            const int wn_l = (wid & 1) * 64;
#pragma unroll
            for (int mi = 0; mi < 2; mi++) {
#pragma unroll
                for (int ni = 0; ni < 8; ni++) {
                    int m = wm + mi * 16 + er;
                    int o = wn_l + ni * 8 + ec;
                    eb[(o    ) * 132 + m    ] = acc[mi][ni][0];
                    eb[(o + 1) * 132 + m    ] = acc[mi][ni][1];
                    eb[(o    ) * 132 + m + 8] = acc[mi][ni][2];
                    eb[(o + 1) * 132 + m + 8] = acc[mi][ni][3];
                }
            }
        }
        __syncthreads();
#pragma unroll
        for (int i = 0; i < 8; i++) {
            int idx = tid + i * 512;
            int r = idx >> 5, c4 = (idx & 31) * 4;
            float4 v = *(const float4*)&eb[r * 132 + c4];
            *(float4*)&out[(size_t)(b * OC + h * 128 + r) * HW + hw0 + c4] = v;
        }
    }
}

// ================= launch =================
extern "C" void kernel_launch(void* const* d_in, const int* in_sizes, int n_in,
                              void* d_out, int out_size)
{
    const float* x      = (const float*)d_in[0];
    const float* w_p    = (const float*)d_in[1];
    const float* b_p    = (const float*)d_in[2];
    const float* w_ad   = (const float*)d_in[3];
    const float* b_ad   = (const float*)d_in[4];
    const float* w_conv = (const float*)d_in[5];
    float* out = (float*)d_out;

    cudaFuncSetAttribute(mma_kernel, cudaFuncAttributeMaxDynamicSharedMemorySize, FUSE_SMEM);

    wq_kernel<<<OC, C>>>(w_conv);
    tr_kernel<<<dim3(HW / 32, C / 32, BDIM), 256>>>(x);
    offset_kernel<<<MPIX / 64, 256>>>(x, w_p, b_p, w_ad, b_ad);
    mma_kernel<<<MPIX / 128, 512, FUSE_SMEM>>>(out);
}

// round 16
// speedup vs baseline: 1.1665x; 1.1665x over previous
#include <cuda_runtime.h>
#include <cuda_bf16.h>
#include <cstdint>

#define BDIM 2
#define C 256
#define H 96
#define W 96
#define HW (H*W)          // 9216
#define MPIX (BDIM*HW)    // 18432
#define OC 256
#define NTAP 9
#define KQ (NTAP*C)       // 2304 logical K
#define KD2 (2*KQ)        // 4608 (hi | lo)
#define HP 98

// -------- scratch (static device globals; no allocations) --------
__device__ __align__(128) __nv_bfloat16 g_Wb2[(size_t)OC * KD2]; // [o][hi|lo] 2.4MB
__device__ __align__(128) float g_xT[(size_t)MPIX * C];          // NHWC x (19MB, L2-resident)
__device__ uint4  g_off4[NTAP * MPIX];   // 4 resolved gather offsets (elements) 2.65MB
__device__ float4 g_w4[NTAP * MPIX];     // masked bilinear weights

// ---------------- PTX helpers (base ISA only) ----------------
__device__ __forceinline__ uint32_t smem_u32(const void* p) {
    uint32_t a;
    asm("{ .reg .u64 t; cvta.to.shared.u64 t, %1; cvt.u32.u64 %0, t; }" : "=r"(a) : "l"(p));
    return a;
}
__device__ __forceinline__ void cp16(uint32_t s, const void* g) {
    asm volatile("cp.async.cg.shared.global [%0], [%1], 16;" :: "r"(s), "l"(g));
}
__device__ __forceinline__ void cp_commit() {
    asm volatile("cp.async.commit_group;" ::: "memory");
}
template <int N> __device__ __forceinline__ void cp_wait() {
    asm volatile("cp.async.wait_group %0;" :: "n"(N) : "memory");
}
__device__ __forceinline__ void sts32(uint32_t a, uint32_t v) {
    asm volatile("st.shared.b32 [%0], %1;" :: "r"(a), "r"(v) : "memory");
}
__device__ __forceinline__ void ldsm_x4(uint32_t* r, uint32_t addr) {
    asm volatile("ldmatrix.sync.aligned.m8n8.x4.shared.b16 {%0,%1,%2,%3}, [%4];"
        : "=r"(r[0]), "=r"(r[1]), "=r"(r[2]), "=r"(r[3]) : "r"(addr));
}
__device__ __forceinline__ void mma16816(float* d, const uint32_t* a, const uint32_t* b) {
    asm volatile("mma.sync.aligned.m16n8k16.row.col.f32.bf16.bf16.f32 "
        "{%0,%1,%2,%3}, {%4,%5,%6,%7}, {%8,%9}, {%0,%1,%2,%3};"
        : "+f"(d[0]), "+f"(d[1]), "+f"(d[2]), "+f"(d[3])
        : "r"(a[0]), "r"(a[1]), "r"(a[2]), "r"(a[3]), "r"(b[0]), "r"(b[1]));
}
__device__ __forceinline__ unsigned long long fma2(
    unsigned long long a, unsigned long long b, unsigned long long c)
{
    unsigned long long d;
    asm("fma.rn.f32x2 %0, %1, %2, %3;" : "=l"(d) : "l"(a), "l"(b), "l"(c));
    return d;
}
__device__ __forceinline__ unsigned long long mul2(
    unsigned long long a, unsigned long long b)
{
    unsigned long long d;
    asm("mul.rn.f32x2 %0, %1, %2;" : "=l"(d) : "l"(a), "l"(b));
    return d;
}
__device__ __forceinline__ unsigned long long pack2(float v) {
    unsigned long long d;
    asm("mov.b64 %0, {%1, %1};" : "=l"(d) : "f"(v));
    return d;
}
__device__ __forceinline__ uint32_t cvt_bf16x2(float hi, float lo) {
    uint32_t r;
    asm("cvt.rn.bf16x2.f32 %0, %1, %2;" : "=r"(r) : "f"(hi), "f"(lo));
    return r;
}
__device__ __forceinline__ uint32_t swz(uint32_t off) { return off ^ ((off >> 3) & 0x70); }

// ================= Kernel 0: weight bf16 hi/lo split =================
__global__ void __launch_bounds__(256) wq_kernel(const float* __restrict__ wc)
{
    int o = blockIdx.x;
    int c = threadIdx.x;
#pragma unroll
    for (int k = 0; k < 9; k++) {
        float w = __ldg(&wc[((size_t)o*C + c)*9 + k]);
        __nv_bfloat16 hi = __float2bfloat16(w);
        __nv_bfloat16 lo = __float2bfloat16(w - __bfloat162float(hi));
        g_Wb2[(size_t)o * KD2 + k*C + c]      = hi;
        g_Wb2[(size_t)o * KD2 + KQ + k*C + c] = lo;
    }
}

// ================= Kernel 0b: NCHW -> NHWC transpose =================
__global__ void __launch_bounds__(256) tr_kernel(const float* __restrict__ x)
{
    __shared__ float tile[32][33];
    const int b   = blockIdx.z;
    const int c0  = blockIdx.y * 32;
    const int hw0 = blockIdx.x * 32;
    const int tx = threadIdx.x & 31;
    const int ty = threadIdx.x >> 5;
#pragma unroll
    for (int r = 0; r < 4; r++) {
        int c = c0 + ty + r * 8;
        tile[ty + r * 8][tx] = x[(size_t)(b * C + c) * HW + hw0 + tx];
    }
    __syncthreads();
#pragma unroll
    for (int r = 0; r < 4; r++) {
        int hw = hw0 + ty + r * 8;
        g_xT[(size_t)(b * HW + hw) * C + c0 + tx] = tile[tx][ty + r * 8];
    }
}

// ================= Kernel 1: offset conv (2 px/lane) + resolved meta =================
__global__ void __launch_bounds__(256) offset_kernel(
    const float* __restrict__ x,  const float* __restrict__ w_p,
    const float* __restrict__ b_p, const float* __restrict__ w_ad,
    const float* __restrict__ b_ad)
{
    const int tid = threadIdx.x;
    const int tx  = tid & 63;
    const int ty  = tid >> 6;
    const int mA  = blockIdx.x * 128 + tx;
    const int mB  = mA + 64;

    __shared__ float wbuf[32][200];
    __shared__ float red[4][21][64];

    const int bA = mA / HW, hwA = mA % HW, hA = hwA / W, wA = hwA % W;
    const int bB = mB / HW, hwB = mB % HW, hB = hwB / W, wB = hwB % W;

    unsigned long long accA[11], accB[11];
#pragma unroll
    for (int i = 0; i < 11; i++) { accA[i] = 0ull; accB[i] = 0ull; }

    if (tid < 32) {
#pragma unroll
        for (int t = 0; t < 9; t++) wbuf[tid][t*22 + 21] = 0.f;
    }

    const float* xA = x + (size_t)bA * C * HW;
    const float* xB = x + (size_t)bB * C * HW;

#pragma unroll 1
    for (int ch = 0; ch < 8; ch++) {
        __syncthreads();
        for (int idx = tid; idx < 32 * 189; idx += 256) {
            int row = idx / 189, e = idx % 189;
            int oc = e / 9, t = e % 9;
            int c = (row >> 3) * 64 + ch * 8 + (row & 7);
            float wv = (oc < 18) ? __ldg(&w_p[((size_t)oc*C + c)*9 + t])
                                 : __ldg(&w_ad[((size_t)(oc-18)*C + c)*9 + t]);
            wbuf[row][t*22 + oc] = wv;
        }
        __syncthreads();
#pragma unroll 1
        for (int cc = 0; cc < 8; cc++) {
            const int c = ty * 64 + ch * 8 + cc;
            const float* plA = xA + (size_t)c * HW;
            const float* plB = xB + (size_t)c * HW;
            float vA[9], vB[9];
#pragma unroll
            for (int t = 0; t < 9; t++) {
                int dh = t / 3 - 1, dw = t % 3 - 1;
                int h1 = hA + dh, w1 = wA + dw;
                vA[t] = (h1 >= 0 && h1 < H && w1 >= 0 && w1 < W) ? __ldg(&plA[h1*W + w1]) : 0.f;
                int h2 = hB + dh, w2 = wB + dw;
                vB[t] = (h2 >= 0 && h2 < H && w2 >= 0 && w2 < W) ? __ldg(&plB[h2*W + w2]) : 0.f;
            }
            const float* wr = &wbuf[ty * 8 + cc][0];
#pragma unroll
            for (int t = 0; t < 9; t++) {
                unsigned long long aA = pack2(vA[t]);
                unsigned long long aB = pack2(vB[t]);
#pragma unroll
                for (int o2 = 0; o2 < 11; o2++) {
                    unsigned long long wpair =
                        *(const unsigned long long*)&wr[t*22 + o2*2];
                    accA[o2] = fma2(wpair, aA, accA[o2]);
                    accB[o2] = fma2(wpair, aB, accB[o2]);
                }
            }
        }
    }

#pragma unroll 1
    for (int p = 0; p < 2; p++) {
        __syncthreads();
#pragma unroll
        for (int o2 = 0; o2 < 11; o2++) {
            unsigned long long v = p ? accB[o2] : accA[o2];
            float lo = __uint_as_float((unsigned)(v & 0xffffffffull));
            float hi = __uint_as_float((unsigned)(v >> 32));
            red[ty][o2*2][tx] = lo;
            if (o2 < 10) red[ty][o2*2+1][tx] = hi;
        }
        __syncthreads();
        if (ty == 0) {
            const int m = (p == 0) ? mA : mB;
            const int h = (p == 0) ? hA : hB;
            const int w = (p == 0) ? wA : wB;
            const unsigned gbase = (unsigned)((p == 0 ? bA : bB) * HW * C);
            float a[21];
#pragma unroll
            for (int oc = 0; oc < 21; oc++)
                a[oc] = red[0][oc][tx] + red[1][oc][tx] + red[2][oc][tx] + red[3][oc][tx];
#pragma unroll
            for (int k = 0; k < 9; k++) {
                float pnx = (float)(k / 3) - 1.f;
                float pny = (float)(k % 3) - 1.f;
                float z   = a[18 + (k % 3)] + __ldg(&b_ad[k % 3]);
                float sig = 1.f / (1.f + expf(-z));
                float ad  = 2.f * (1.f - sig);
                float px = (float)(h + 1) + pnx + a[k]     + __ldg(&b_p[k])     + ad * pnx;
                float py = (float)(w + 1) + pny + a[9 + k] + __ldg(&b_p[9 + k]) + ad * pny;
                float fx = floorf(px), fy = floorf(py);
                int iltx = (int)fx, ilty = (int)fy;
                int ltx = min(max(iltx,     0), HP - 1), lty = min(max(ilty,     0), HP - 1);
                int rbx = min(max(iltx + 1, 0), HP - 1), rby = min(max(ilty + 1, 0), HP - 1);
                bool mx = (px < 1.f) || (px > (float)(HP - 2));
                bool my = (py < 1.f) || (py > (float)(HP - 2));
                if (mx) px = fx;
                if (my) py = fy;
                px = fminf(fmaxf(px, 0.f), (float)(HP - 1));
                py = fminf(fmaxf(py, 0.f), (float)(HP - 1));
                float dxl = 1.f + ((float)ltx - px);
                float dyl = 1.f + ((float)lty - py);
                float dxr = 1.f - ((float)rbx - px);
                float dyr = 1.f - ((float)rby - py);
                // resolve masks + offsets NOW (hot loop reads these directly)
                const bool ax  = (ltx >= 1) && (ltx <= 96);
                const bool axr = (rbx >= 1) && (rbx <= 96);
                const bool ay  = (lty >= 1) && (lty <= 96);
                const bool ayr = (rby >= 1) && (rby <= 96);
                float4 wm;
                wm.x = (ax  && ay ) ? dxl*dyl : 0.f;   // LT
                wm.y = (axr && ayr) ? dxr*dyr : 0.f;   // RB
                wm.z = (ax  && ayr) ? dxl*dyr : 0.f;   // LB
                wm.w = (axr && ay ) ? dxr*dyl : 0.f;   // RT
                uint4 off;
                off.x = (ax  && ay ) ? gbase + (unsigned)((ltx-1)*W + (lty-1)) * C : gbase;
                off.y = (axr && ayr) ? gbase + (unsigned)((rbx-1)*W + (rby-1)) * C : gbase;
                off.z = (ax  && ayr) ? gbase + (unsigned)((ltx-1)*W + (rby-1)) * C : gbase;
                off.w = (axr && ay ) ? gbase + (unsigned)((rbx-1)*W + (lty-1)) * C : gbase;
                g_off4[k*MPIX + m] = off;
                g_w4[k*MPIX + m]   = wm;
            }
        }
    }
}

// ================= Kernel 2: fused sample + HMMA GEMM, prefetch-pipelined =================
// CTA: 128 m x 256 o, 512 threads (16 warps, warp tile 32m x 64o), grid 144.
// chunk = 32 channels of one tap -> 72 chunks. Tile rows 64B wide (SW swizzled).
#define NCH 72
#define ST_AH 0
#define ST_AL 8192
#define ST_BH 16384
#define ST_BL 32768
#define STAGE 49152
#define FUSE_SMEM (2 * STAGE)    // 96KB

struct APre {
    unsigned long long v[2][4];   // packed float2 corner pairs
    float w[2][4];
};

__device__ __forceinline__ void a_issue(APre& P, int tap, int c0, int m0,
                                        int rg, int cl, int h)
{
#pragma unroll
    for (int j = 0; j < 2; j++) {
        const int m_l = rg * 4 + h * 2 + j;
        const int m = m0 + m_l;
        const uint4  off = g_off4[tap*MPIX + m];
        const float4 wm  = g_w4[tap*MPIX + m];
        P.w[j][0] = wm.x; P.w[j][1] = wm.y; P.w[j][2] = wm.z; P.w[j][3] = wm.w;
        const int cix = c0 + cl * 2;
        P.v[j][0] = *(const unsigned long long*)&g_xT[off.x + cix];
        P.v[j][1] = *(const unsigned long long*)&g_xT[off.y + cix];
        P.v[j][2] = *(const unsigned long long*)&g_xT[off.z + cix];
        P.v[j][3] = *(const unsigned long long*)&g_xT[off.w + cix];
    }
}

__device__ __forceinline__ void a_store(APre& P, uint32_t stgN, int rg, int cl, int h)
{
#pragma unroll
    for (int j = 0; j < 2; j++) {
        const int m_l = rg * 4 + h * 2 + j;
        unsigned long long v01 = mul2(pack2(P.w[j][0]), P.v[j][0]);
        v01 = fma2(pack2(P.w[j][1]), P.v[j][1], v01);
        v01 = fma2(pack2(P.w[j][2]), P.v[j][2], v01);
        v01 = fma2(pack2(P.w[j][3]), P.v[j][3], v01);
        float v0 = __uint_as_float((unsigned)(v01 & 0xffffffffull));
        float v1 = __uint_as_float((unsigned)(v01 >> 32));
        uint32_t hw_ = cvt_bf16x2(v1, v0);
        __nv_bfloat162 hh = *reinterpret_cast<__nv_bfloat162*>(&hw_);
        float l0 = v0 - __bfloat162float(hh.x);
        float l1 = v1 - __bfloat162float(hh.y);
        uint32_t lw_ = cvt_bf16x2(l1, l0);
        uint32_t off = swz((uint32_t)(m_l * 64 + cl * 4));
        sts32(stgN + ST_AH + off, hw_);
        sts32(stgN + ST_AL + off, lw_);
    }
}

__device__ __forceinline__ void produce_B(uint32_t stg, int t, int tid)
{
    const char* Wb = (const char*)g_Wb2;
    const int colb = (t >> 3) * 512 + (t & 7) * 64;
#pragma unroll
    for (int j = 0; j < 4; j++) {
        int idx = tid + j * 512;            // 0..2047
        int part = idx >> 10;               // 0: hi, 1: lo
        int within = idx & 1023;
        int o = within >> 2, cc = within & 3;
        uint32_t dst = stg + ST_BH + part * 16384 + swz((uint32_t)(o * 64 + cc * 16));
        cp16(dst, Wb + (size_t)o * (KD2 * 2) + part * (KQ * 2) + colb + cc * 16);
    }
}

__global__ void __launch_bounds__(512, 1) mma_kernel(float* __restrict__ out)
{
    extern __shared__ char smem[];
    const uint32_t sb = smem_u32(smem);
    const int tid = threadIdx.x;
    const int wid = tid >> 5, lane = tid & 31;
    const int m0 = blockIdx.x * 128;

    const int wm = (wid >> 2) * 32;
    const int wn = (wid & 3) * 64;
    const int rg = tid >> 4;
    const int cl = tid & 15;

    float acc[2][8][4];
#pragma unroll
    for (int mi = 0; mi < 2; mi++)
#pragma unroll
        for (int ni = 0; ni < 8; ni++)
#pragma unroll
            for (int r = 0; r < 4; r++) acc[mi][ni][r] = 0.f;

    const int a_row = wm + (lane & 15);
    const int a_cb  = (lane >> 4) * 16;
    const int b_row = wn + (lane & 7) + ((lane >> 4) << 3);
    const int b_cb  = ((lane >> 3) & 1) * 16;

    // ---- prologue: chunk 0 ----
    produce_B(sb, 0, tid);
    cp_commit();
    {
        APre P;
        a_issue(P, 0, 0, m0, rg, cl, 0);
        a_store(P, sb, rg, cl, 0);
        a_issue(P, 0, 0, m0, rg, cl, 1);
        a_store(P, sb, rg, cl, 1);
    }

#pragma unroll 1
    for (int t = 0; t < NCH; t++) {
        const uint32_t stg  = sb + (t & 1) * STAGE;
        const uint32_t stgN = sb + ((t + 1) & 1) * STAGE;
        __syncthreads();
        if (t + 1 < NCH) produce_B(stgN, t + 1, tid);
        cp_commit();
        cp_wait<1>();
        __syncthreads();

        const int tapN = (t + 1) >> 3;
        const int c0N  = ((t + 1) & 7) * 32;
        const bool more = (t + 1 < NCH);

        APre P;
        if (more) a_issue(P, tapN, c0N, m0, rg, cl, 0);

        const uint32_t Ah = stg + ST_AH;
        const uint32_t Al = stg + ST_AL;
        const uint32_t Bh = stg + ST_BH;
        const uint32_t Bl = stg + ST_BL;

#pragma unroll 1
        for (int kk = 0; kk < 2; kk++) {
            const int kb = kk * 32;
            uint32_t ah[2][4], al[2][4], bf[4][4];
#pragma unroll
            for (int mi = 0; mi < 2; mi++)
                ldsm_x4(ah[mi], Ah + swz((uint32_t)((a_row + mi * 16) * 64 + kb + a_cb)));
#pragma unroll
            for (int nb = 0; nb < 4; nb++)
                ldsm_x4(bf[nb], Bh + swz((uint32_t)((b_row + nb * 16) * 64 + kb + b_cb)));
#pragma unroll
            for (int mi = 0; mi < 2; mi++)
#pragma unroll
                for (int ni = 0; ni < 8; ni++)
                    mma16816(acc[mi][ni], ah[mi], &bf[ni >> 1][(ni & 1) * 2]);
#pragma unroll
            for (int mi = 0; mi < 2; mi++)
                ldsm_x4(al[mi], Al + swz((uint32_t)((a_row + mi * 16) * 64 + kb + a_cb)));
#pragma unroll
            for (int mi = 0; mi < 2; mi++)
#pragma unroll
                for (int ni = 0; ni < 8; ni++)
                    mma16816(acc[mi][ni], al[mi], &bf[ni >> 1][(ni & 1) * 2]);
#pragma unroll
            for (int nb = 0; nb < 4; nb++)
                ldsm_x4(bf[nb], Bl + swz((uint32_t)((b_row + nb * 16) * 64 + kb + b_cb)));
#pragma unroll
            for (int mi = 0; mi < 2; mi++)
#pragma unroll
                for (int ni = 0; ni < 8; ni++)
                    mma16816(acc[mi][ni], ah[mi], &bf[ni >> 1][(ni & 1) * 2]);

            if (more) {
                a_store(P, stgN, rg, cl, kk);
                if (kk == 0) a_issue(P, tapN, c0N, m0, rg, cl, 1);
            }
        }
    }

    // ---- epilogue ----
    const int b   = m0 / HW;
    const int hw0 = m0 % HW;
    float* eb = (float*)smem;
    const int er = lane >> 2;
    const int ec = (lane & 3) * 2;
#pragma unroll 1
    for (int h = 0; h < 2; h++) {
        __syncthreads();
        if (((wid & 3) >> 1) == h) {
            const int wn_l = (wid & 1) * 64;
#pragma unroll
            for (int mi = 0; mi < 2; mi++) {
#pragma unroll
                for (int ni = 0; ni < 8; ni++) {
                    int m = wm + mi * 16 + er;
                    int o = wn_l + ni * 8 + ec;
                    eb[(o    ) * 132 + m    ] = acc[mi][ni][0];
                    eb[(o + 1) * 132 + m    ] = acc[mi][ni][1];
                    eb[(o    ) * 132 + m + 8] = acc[mi][ni][2];
                    eb[(o + 1) * 132 + m + 8] = acc[mi][ni][3];
                }
            }
        }
        __syncthreads();
#pragma unroll
        for (int i = 0; i < 8; i++) {
            int idx = tid + i * 512;
            int r = idx >> 5, c4 = (idx & 31) * 4;
            float4 v = *(const float4*)&eb[r * 132 + c4];
            *(float4*)&out[(size_t)(b * OC + h * 128 + r) * HW + hw0 + c4] = v;
        }
    }
}

// ================= launch =================
extern "C" void kernel_launch(void* const* d_in, const int* in_sizes, int n_in,
                              void* d_out, int out_size)
{
    const float* x      = (const float*)d_in[0];
    const float* w_p    = (const float*)d_in[1];
    const float* b_p    = (const float*)d_in[2];
    const float* w_ad   = (const float*)d_in[3];
    const float* b_ad   = (const float*)d_in[4];
    const float* w_conv = (const float*)d_in[5];
    float* out = (float*)d_out;

    cudaFuncSetAttribute(mma_kernel, cudaFuncAttributeMaxDynamicSharedMemorySize, FUSE_SMEM);

    wq_kernel<<<OC, C>>>(w_conv);
    tr_kernel<<<dim3(HW / 32, C / 32, BDIM), 256>>>(x);
    offset_kernel<<<MPIX / 128, 256>>>(x, w_p, b_p, w_ad, b_ad);
    mma_kernel<<<MPIX / 128, 512, FUSE_SMEM>>>(out);
}

// round 17
// speedup vs baseline: 1.2137x; 1.0405x over previous
#include <cuda_runtime.h>
#include <cuda_bf16.h>
#include <cstdint>

#define BDIM 2
#define C 256
#define H 96
#define W 96
#define HW (H*W)          // 9216
#define MPIX (BDIM*HW)    // 18432
#define OC 256
#define NTAP 9
#define KQ (NTAP*C)       // 2304 logical K
#define KD2 (2*KQ)        // 4608 (hi | lo)
#define HP 98

// -------- scratch (static device globals; no allocations) --------
__device__ __align__(128) __nv_bfloat16 g_Wb2[(size_t)OC * KD2]; // [o][hi|lo] 2.4MB
__device__ __align__(128) float g_xT[(size_t)MPIX * C];          // NHWC x (19MB, L2-resident)
__device__ uint4  g_off4[NTAP * MPIX];   // 4 resolved gather offsets (elements) 2.65MB
__device__ float4 g_w4[NTAP * MPIX];     // masked bilinear weights

// ---------------- PTX helpers (base ISA only) ----------------
__device__ __forceinline__ uint32_t smem_u32(const void* p) {
    uint32_t a;
    asm("{ .reg .u64 t; cvta.to.shared.u64 t, %1; cvt.u32.u64 %0, t; }" : "=r"(a) : "l"(p));
    return a;
}
__device__ __forceinline__ void cp16(uint32_t s, const void* g) {
    asm volatile("cp.async.cg.shared.global [%0], [%1], 16;" :: "r"(s), "l"(g));
}
__device__ __forceinline__ void cp_commit() {
    asm volatile("cp.async.commit_group;" ::: "memory");
}
template <int N> __device__ __forceinline__ void cp_wait() {
    asm volatile("cp.async.wait_group %0;" :: "n"(N) : "memory");
}
__device__ __forceinline__ void sts32(uint32_t a, uint32_t v) {
    asm volatile("st.shared.b32 [%0], %1;" :: "r"(a), "r"(v) : "memory");
}
__device__ __forceinline__ void ldsm_x4(uint32_t* r, uint32_t addr) {
    asm volatile("ldmatrix.sync.aligned.m8n8.x4.shared.b16 {%0,%1,%2,%3}, [%4];"
        : "=r"(r[0]), "=r"(r[1]), "=r"(r[2]), "=r"(r[3]) : "r"(addr));
}
__device__ __forceinline__ void mma16816(float* d, const uint32_t* a, const uint32_t* b) {
    asm volatile("mma.sync.aligned.m16n8k16.row.col.f32.bf16.bf16.f32 "
        "{%0,%1,%2,%3}, {%4,%5,%6,%7}, {%8,%9}, {%0,%1,%2,%3};"
        : "+f"(d[0]), "+f"(d[1]), "+f"(d[2]), "+f"(d[3])
        : "r"(a[0]), "r"(a[1]), "r"(a[2]), "r"(a[3]), "r"(b[0]), "r"(b[1]));
}
__device__ __forceinline__ unsigned long long fma2(
    unsigned long long a, unsigned long long b, unsigned long long c)
{
    unsigned long long d;
    asm("fma.rn.f32x2 %0, %1, %2, %3;" : "=l"(d) : "l"(a), "l"(b), "l"(c));
    return d;
}
__device__ __forceinline__ unsigned long long mul2(
    unsigned long long a, unsigned long long b)
{
    unsigned long long d;
    asm("mul.rn.f32x2 %0, %1, %2;" : "=l"(d) : "l"(a), "l"(b));
    return d;
}
__device__ __forceinline__ unsigned long long pack2(float v) {
    unsigned long long d;
    asm("mov.b64 %0, {%1, %1};" : "=l"(d) : "f"(v));
    return d;
}
__device__ __forceinline__ uint32_t cvt_bf16x2(float hi, float lo) {
    uint32_t r;
    asm("cvt.rn.bf16x2.f32 %0, %1, %2;" : "=r"(r) : "f"(hi), "f"(lo));
    return r;
}
__device__ __forceinline__ uint32_t swz(uint32_t off) { return off ^ ((off >> 3) & 0x70); }

// ================= Kernel 0: weight bf16 hi/lo split =================
__global__ void __launch_bounds__(256) wq_kernel(const float* __restrict__ wc)
{
    int o = blockIdx.x;
    int c = threadIdx.x;
#pragma unroll
    for (int k = 0; k < 9; k++) {
        float w = __ldg(&wc[((size_t)o*C + c)*9 + k]);
        __nv_bfloat16 hi = __float2bfloat16(w);
        __nv_bfloat16 lo = __float2bfloat16(w - __bfloat162float(hi));
        g_Wb2[(size_t)o * KD2 + k*C + c]      = hi;
        g_Wb2[(size_t)o * KD2 + KQ + k*C + c] = lo;
    }
}

// ================= Kernel 0b: NCHW -> NHWC transpose =================
__global__ void __launch_bounds__(256) tr_kernel(const float* __restrict__ x)
{
    __shared__ float tile[32][33];
    const int b   = blockIdx.z;
    const int c0  = blockIdx.y * 32;
    const int hw0 = blockIdx.x * 32;
    const int tx = threadIdx.x & 31;
    const int ty = threadIdx.x >> 5;
#pragma unroll
    for (int r = 0; r < 4; r++) {
        int c = c0 + ty + r * 8;
        tile[ty + r * 8][tx] = x[(size_t)(b * C + c) * HW + hw0 + tx];
    }
    __syncthreads();
#pragma unroll
    for (int r = 0; r < 4; r++) {
        int hw = hw0 + ty + r * 8;
        g_xT[(size_t)(b * HW + hw) * C + c0 + tx] = tile[tx][ty + r * 8];
    }
}

// ================= Kernel 1: offset conv (2 px/lane) + resolved meta =================
__global__ void __launch_bounds__(256) offset_kernel(
    const float* __restrict__ x,  const float* __restrict__ w_p,
    const float* __restrict__ b_p, const float* __restrict__ w_ad,
    const float* __restrict__ b_ad)
{
    const int tid = threadIdx.x;
    const int tx  = tid & 63;
    const int ty  = tid >> 6;
    const int mA  = blockIdx.x * 128 + tx;
    const int mB  = mA + 64;

    __shared__ float wbuf[32][200];
    __shared__ float red[4][21][64];

    const int bA = mA / HW, hwA = mA % HW, hA = hwA / W, wA = hwA % W;
    const int bB = mB / HW, hwB = mB % HW, hB = hwB / W, wB = hwB % W;

    unsigned long long accA[11], accB[11];
#pragma unroll
    for (int i = 0; i < 11; i++) { accA[i] = 0ull; accB[i] = 0ull; }

    if (tid < 32) {
#pragma unroll
        for (int t = 0; t < 9; t++) wbuf[tid][t*22 + 21] = 0.f;
    }

    const float* xA = x + (size_t)bA * C * HW;
    const float* xB = x + (size_t)bB * C * HW;

#pragma unroll 1
    for (int ch = 0; ch < 8; ch++) {
        __syncthreads();
        for (int idx = tid; idx < 32 * 189; idx += 256) {
            int row = idx / 189, e = idx % 189;
            int oc = e / 9, t = e % 9;
            int c = (row >> 3) * 64 + ch * 8 + (row & 7);
            float wv = (oc < 18) ? __ldg(&w_p[((size_t)oc*C + c)*9 + t])
                                 : __ldg(&w_ad[((size_t)(oc-18)*C + c)*9 + t]);
            wbuf[row][t*22 + oc] = wv;
        }
        __syncthreads();
#pragma unroll 1
        for (int cc = 0; cc < 8; cc++) {
            const int c = ty * 64 + ch * 8 + cc;
            const float* plA = xA + (size_t)c * HW;
            const float* plB = xB + (size_t)c * HW;
            float vA[9], vB[9];
#pragma unroll
            for (int t = 0; t < 9; t++) {
                int dh = t / 3 - 1, dw = t % 3 - 1;
                int h1 = hA + dh, w1 = wA + dw;
                vA[t] = (h1 >= 0 && h1 < H && w1 >= 0 && w1 < W) ? __ldg(&plA[h1*W + w1]) : 0.f;
                int h2 = hB + dh, w2 = wB + dw;
                vB[t] = (h2 >= 0 && h2 < H && w2 >= 0 && w2 < W) ? __ldg(&plB[h2*W + w2]) : 0.f;
            }
            const float* wr = &wbuf[ty * 8 + cc][0];
#pragma unroll
            for (int t = 0; t < 9; t++) {
                unsigned long long aA = pack2(vA[t]);
                unsigned long long aB = pack2(vB[t]);
#pragma unroll
                for (int o2 = 0; o2 < 11; o2++) {
                    unsigned long long wpair =
                        *(const unsigned long long*)&wr[t*22 + o2*2];
                    accA[o2] = fma2(wpair, aA, accA[o2]);
                    accB[o2] = fma2(wpair, aB, accB[o2]);
                }
            }
        }
    }

#pragma unroll 1
    for (int p = 0; p < 2; p++) {
        __syncthreads();
#pragma unroll
        for (int o2 = 0; o2 < 11; o2++) {
            unsigned long long v = p ? accB[o2] : accA[o2];
            float lo = __uint_as_float((unsigned)(v & 0xffffffffull));
            float hi = __uint_as_float((unsigned)(v >> 32));
            red[ty][o2*2][tx] = lo;
            if (o2 < 10) red[ty][o2*2+1][tx] = hi;
        }
        __syncthreads();
        if (ty == 0) {
            const int m = (p == 0) ? mA : mB;
            const int h = (p == 0) ? hA : hB;
            const int w = (p == 0) ? wA : wB;
            const unsigned gbase = (unsigned)((p == 0 ? bA : bB) * HW * C);
            float a[21];
#pragma unroll
            for (int oc = 0; oc < 21; oc++)
                a[oc] = red[0][oc][tx] + red[1][oc][tx] + red[2][oc][tx] + red[3][oc][tx];
#pragma unroll
            for (int k = 0; k < 9; k++) {
                float pnx = (float)(k / 3) - 1.f;
                float pny = (float)(k % 3) - 1.f;
                float z   = a[18 + (k % 3)] + __ldg(&b_ad[k % 3]);
                float sig = 1.f / (1.f + expf(-z));
                float ad  = 2.f * (1.f - sig);
                float px = (float)(h + 1) + pnx + a[k]     + __ldg(&b_p[k])     + ad * pnx;
                float py = (float)(w + 1) + pny + a[9 + k] + __ldg(&b_p[9 + k]) + ad * pny;
                float fx = floorf(px), fy = floorf(py);
                int iltx = (int)fx, ilty = (int)fy;
                int ltx = min(max(iltx,     0), HP - 1), lty = min(max(ilty,     0), HP - 1);
                int rbx = min(max(iltx + 1, 0), HP - 1), rby = min(max(ilty + 1, 0), HP - 1);
                bool mx = (px < 1.f) || (px > (float)(HP - 2));
                bool my = (py < 1.f) || (py > (float)(HP - 2));
                if (mx) px = fx;
                if (my) py = fy;
                px = fminf(fmaxf(px, 0.f), (float)(HP - 1));
                py = fminf(fmaxf(py, 0.f), (float)(HP - 1));
                float dxl = 1.f + ((float)ltx - px);
                float dyl = 1.f + ((float)lty - py);
                float dxr = 1.f - ((float)rbx - px);
                float dyr = 1.f - ((float)rby - py);
                const bool ax  = (ltx >= 1) && (ltx <= 96);
                const bool axr = (rbx >= 1) && (rbx <= 96);
                const bool ay  = (lty >= 1) && (lty <= 96);
                const bool ayr = (rby >= 1) && (rby <= 96);
                float4 wm;
                wm.x = (ax  && ay ) ? dxl*dyl : 0.f;
                wm.y = (axr && ayr) ? dxr*dyr : 0.f;
                wm.z = (ax  && ayr) ? dxl*dyr : 0.f;
                wm.w = (axr && ay ) ? dxr*dyl : 0.f;
                uint4 off;
                off.x = (ax  && ay ) ? gbase + (unsigned)((ltx-1)*W + (lty-1)) * C : gbase;
                off.y = (axr && ayr) ? gbase + (unsigned)((rbx-1)*W + (rby-1)) * C : gbase;
                off.z = (ax  && ayr) ? gbase + (unsigned)((ltx-1)*W + (rby-1)) * C : gbase;
                off.w = (axr && ay ) ? gbase + (unsigned)((rbx-1)*W + (lty-1)) * C : gbase;
                g_off4[k*MPIX + m] = off;
                g_w4[k*MPIX + m]   = wm;
            }
        }
    }
}

// ================= Kernel 2: fused sample + HMMA GEMM, 3-stage / 1 barrier =================
// CTA: 128 m x 256 o, 512 threads (16 warps, warp tile 32m x 64o), grid 144.
// chunk = 32 channels of one tap -> 72 chunks. Tile rows 64B wide (SW swizzled).
#define NCH 72
#define ST_AH 0
#define ST_AL 8192
#define ST_BH 16384
#define ST_BL 32768
#define STAGE 49152
#define NSTG 3
#define FUSE_SMEM (NSTG * STAGE)    // 144KB

struct APre {
    unsigned long long v[2][4];   // packed float2 corner pairs
    float w[2][4];
};

__device__ __forceinline__ void a_issue(APre& P, int tap, int c0, int m0,
                                        int rg, int cl, int h)
{
#pragma unroll
    for (int j = 0; j < 2; j++) {
        const int m_l = rg * 4 + h * 2 + j;
        const int m = m0 + m_l;
        const uint4  off = g_off4[tap*MPIX + m];
        const float4 wm  = g_w4[tap*MPIX + m];
        P.w[j][0] = wm.x; P.w[j][1] = wm.y; P.w[j][2] = wm.z; P.w[j][3] = wm.w;
        const int cix = c0 + cl * 2;
        P.v[j][0] = *(const unsigned long long*)&g_xT[off.x + cix];
        P.v[j][1] = *(const unsigned long long*)&g_xT[off.y + cix];
        P.v[j][2] = *(const unsigned long long*)&g_xT[off.z + cix];
        P.v[j][3] = *(const unsigned long long*)&g_xT[off.w + cix];
    }
}

__device__ __forceinline__ void a_store(APre& P, uint32_t stgN, int rg, int cl, int h)
{
#pragma unroll
    for (int j = 0; j < 2; j++) {
        const int m_l = rg * 4 + h * 2 + j;
        unsigned long long v01 = mul2(pack2(P.w[j][0]), P.v[j][0]);
        v01 = fma2(pack2(P.w[j][1]), P.v[j][1], v01);
        v01 = fma2(pack2(P.w[j][2]), P.v[j][2], v01);
        v01 = fma2(pack2(P.w[j][3]), P.v[j][3], v01);
        float v0 = __uint_as_float((unsigned)(v01 & 0xffffffffull));
        float v1 = __uint_as_float((unsigned)(v01 >> 32));
        uint32_t hw_ = cvt_bf16x2(v1, v0);
        __nv_bfloat162 hh = *reinterpret_cast<__nv_bfloat162*>(&hw_);
        float l0 = v0 - __bfloat162float(hh.x);
        float l1 = v1 - __bfloat162float(hh.y);
        uint32_t lw_ = cvt_bf16x2(l1, l0);
        uint32_t off = swz((uint32_t)(m_l * 64 + cl * 4));
        sts32(stgN + ST_AH + off, hw_);
        sts32(stgN + ST_AL + off, lw_);
    }
}

__device__ __forceinline__ void produce_B(uint32_t stg, int t, int tid)
{
    const char* Wb = (const char*)g_Wb2;
    const int colb = (t >> 3) * 512 + (t & 7) * 64;
#pragma unroll
    for (int j = 0; j < 4; j++) {
        int idx = tid + j * 512;            // 0..2047
        int part = idx >> 10;               // 0: hi, 1: lo
        int within = idx & 1023;
        int o = within >> 2, cc = within & 3;
        uint32_t dst = stg + ST_BH + part * 16384 + swz((uint32_t)(o * 64 + cc * 16));
        cp16(dst, Wb + (size_t)o * (KD2 * 2) + part * (KQ * 2) + colb + cc * 16);
    }
}

__global__ void __launch_bounds__(512, 1) mma_kernel(float* __restrict__ out)
{
    extern __shared__ char smem[];
    const uint32_t sb = smem_u32(smem);
    const int tid = threadIdx.x;
    const int wid = tid >> 5, lane = tid & 31;
    const int m0 = blockIdx.x * 128;

    const int wm = (wid >> 2) * 32;
    const int wn = (wid & 3) * 64;
    const int rg = tid >> 4;
    const int cl = tid & 15;

    float acc[2][8][4];
#pragma unroll
    for (int mi = 0; mi < 2; mi++)
#pragma unroll
        for (int ni = 0; ni < 8; ni++)
#pragma unroll
            for (int r = 0; r < 4; r++) acc[mi][ni][r] = 0.f;

    const int a_row = wm + (lane & 15);
    const int a_cb  = (lane >> 4) * 16;
    const int b_row = wn + (lane & 7) + ((lane >> 4) << 3);
    const int b_cb  = ((lane >> 3) & 1) * 16;

    // ---- prologue: chunk 0 into stage 0 ----
    produce_B(sb, 0, tid);
    cp_commit();
    {
        APre P;
        a_issue(P, 0, 0, m0, rg, cl, 0);
        a_store(P, sb, rg, cl, 0);
        a_issue(P, 0, 0, m0, rg, cl, 1);
        a_store(P, sb, rg, cl, 1);
    }

    int s = 0;                      // stage of chunk t
#pragma unroll 1
    for (int t = 0; t < NCH; t++) {
        const int sN = (s + 1 == NSTG) ? 0 : s + 1;
        const uint32_t stg  = sb + s  * STAGE;
        const uint32_t stgN = sb + sN * STAGE;
        // produce B(t+1) into stage sN (consumed at t-2; safe after barrier(t-1))
        if (t + 1 < NCH) produce_B(stgN, t + 1, tid);
        cp_commit();
        cp_wait<1>();               // B(t) landed (this thread's copies)
        __syncthreads();            // B(t) + A(t) stores visible; t-1 consumption done

        const int tapN = (t + 1) >> 3;
        const int c0N  = ((t + 1) & 7) * 32;
        const bool more = (t + 1 < NCH);

        APre P;
        if (more) a_issue(P, tapN, c0N, m0, rg, cl, 0);

        const uint32_t Ah = stg + ST_AH;
        const uint32_t Al = stg + ST_AL;
        const uint32_t Bh = stg + ST_BH;
        const uint32_t Bl = stg + ST_BL;

#pragma unroll 1
        for (int kk = 0; kk < 2; kk++) {
            const int kb = kk * 32;
            uint32_t ah[2][4], al[2][4], bf[4][4];
#pragma unroll
            for (int mi = 0; mi < 2; mi++)
                ldsm_x4(ah[mi], Ah + swz((uint32_t)((a_row + mi * 16) * 64 + kb + a_cb)));
#pragma unroll
            for (int nb = 0; nb < 4; nb++)
                ldsm_x4(bf[nb], Bh + swz((uint32_t)((b_row + nb * 16) * 64 + kb + b_cb)));
#pragma unroll
            for (int mi = 0; mi < 2; mi++)
#pragma unroll
                for (int ni = 0; ni < 8; ni++)
                    mma16816(acc[mi][ni], ah[mi], &bf[ni >> 1][(ni & 1) * 2]);
#pragma unroll
            for (int mi = 0; mi < 2; mi++)
                ldsm_x4(al[mi], Al + swz((uint32_t)((a_row + mi * 16) * 64 + kb + a_cb)));
#pragma unroll
            for (int mi = 0; mi < 2; mi++)
#pragma unroll
                for (int ni = 0; ni < 8; ni++)
                    mma16816(acc[mi][ni], al[mi], &bf[ni >> 1][(ni & 1) * 2]);
#pragma unroll
            for (int nb = 0; nb < 4; nb++)
                ldsm_x4(bf[nb], Bl + swz((uint32_t)((b_row + nb * 16) * 64 + kb + b_cb)));
#pragma unroll
            for (int mi = 0; mi < 2; mi++)
#pragma unroll
                for (int ni = 0; ni < 8; ni++)
                    mma16816(acc[mi][ni], ah[mi], &bf[ni >> 1][(ni & 1) * 2]);

            if (more) {
                a_store(P, stgN, rg, cl, kk);
                if (kk == 0) a_issue(P, tapN, c0N, m0, rg, cl, 1);
            }
        }
        s = sN;
    }

    // ---- epilogue ----
    const int b   = m0 / HW;
    const int hw0 = m0 % HW;
    float* eb = (float*)smem;
    const int er = lane >> 2;
    const int ec = (lane & 3) * 2;
#pragma unroll 1
    for (int h = 0; h < 2; h++) {
        __syncthreads();
        if (((wid & 3) >> 1) == h) {
            const int wn_l = (wid & 1) * 64;
#pragma unroll
            for (int mi = 0; mi < 2; mi++) {
#pragma unroll
                for (int ni = 0; ni < 8; ni++) {
                    int m = wm + mi * 16 + er;
                    int o = wn_l + ni * 8 + ec;
                    eb[(o    ) * 132 + m    ] = acc[mi][ni][0];
                    eb[(o + 1) * 132 + m    ] = acc[mi][ni][1];
                    eb[(o    ) * 132 + m + 8] = acc[mi][ni][2];
                    eb[(o + 1) * 132 + m + 8] = acc[mi][ni][3];
                }
            }
        }
        __syncthreads();
#pragma unroll
        for (int i = 0; i < 8; i++) {
            int idx = tid + i * 512;
            int r = idx >> 5, c4 = (idx & 31) * 4;
            float4 v = *(const float4*)&eb[r * 132 + c4];
            *(float4*)&out[(size_t)(b * OC + h * 128 + r) * HW + hw0 + c4] = v;
        }
    }
}

// ================= launch =================
extern "C" void kernel_launch(void* const* d_in, const int* in_sizes, int n_in,
                              void* d_out, int out_size)
{
    const float* x      = (const float*)d_in[0];
    const float* w_p    = (const float*)d_in[1];
    const float* b_p    = (const float*)d_in[2];
    const float* w_ad   = (const float*)d_in[3];
    const float* b_ad   = (const float*)d_in[4];
    const float* w_conv = (const float*)d_in[5];
    float* out = (float*)d_out;

    cudaFuncSetAttribute(mma_kernel, cudaFuncAttributeMaxDynamicSharedMemorySize, FUSE_SMEM);

    wq_kernel<<<OC, C>>>(w_conv);
    tr_kernel<<<dim3(HW / 32, C / 32, BDIM), 256>>>(x);
    offset_kernel<<<MPIX / 128, 256>>>(x, w_p, b_p, w_ad, b_ad);
    mma_kernel<<<MPIX / 128, 512, FUSE_SMEM>>>(out);
}